// round 1
// baseline (speedup 1.0000x reference)
#include <cuda_runtime.h>
#include <math.h>

#define N_NODES  50000
#define N_EDGES  800000
#define E_TOT    850000      // edges + self loops
#define N_GRAPHS 64
#define D        128
#define N_CLASSES 10
#define NEG_SLOPE 0.2f

// ----------------------------- scratch (device globals; no allocs) ---------
__device__ float g_buf0[N_NODES * D];
__device__ float g_buf1[N_NODES * D];
__device__ float g_xl[N_NODES * D];
__device__ float g_xr[N_NODES * D];
__device__ int   g_deg[N_NODES];
__device__ int   g_off[N_NODES + 1];
__device__ int   g_cur[N_NODES];
__device__ int   g_srcs[E_TOT];
__device__ float g_psum[N_GRAPHS * D];
__device__ int   g_pcnt[N_GRAPHS];

__device__ __forceinline__ float lrelu(float v) { return v > 0.f ? v : NEG_SLOPE * v; }
__device__ __forceinline__ float elu(float v)   { return v > 0.f ? v : __expf(v) - 1.f; }

// ----------------------------- init: copy x, reset counters ----------------
__global__ void k_init(const float* __restrict__ x) {
    int i = blockIdx.x * blockDim.x + threadIdx.x;
    int n4 = N_NODES * D / 4;
    if (i < n4) ((float4*)g_buf0)[i] = ((const float4*)x)[i];
    if (i < N_NODES) g_deg[i] = 1;                 // self loop
    if (i < N_GRAPHS * D) g_psum[i] = 0.f;
    if (i < N_GRAPHS) g_pcnt[i] = 0;
}

// ----------------------------- CSR build -----------------------------------
__global__ void k_count(const int* __restrict__ ei) {
    int e = blockIdx.x * blockDim.x + threadIdx.x;
    if (e < N_EDGES) atomicAdd(&g_deg[ei[N_EDGES + e]], 1);
}

// single-block exclusive scan over g_deg -> g_off, g_cur
__global__ void k_scan() {
    __shared__ int sh[1024];
    __shared__ int carry_s;
    int t = threadIdx.x;
    if (t == 0) carry_s = 0;
    __syncthreads();
    for (int base = 0; base < N_NODES; base += 1024) {
        int idx = base + t;
        int v = (idx < N_NODES) ? g_deg[idx] : 0;
        sh[t] = v;
        __syncthreads();
        #pragma unroll
        for (int off = 1; off < 1024; off <<= 1) {
            int add = (t >= off) ? sh[t - off] : 0;
            __syncthreads();
            sh[t] += add;
            __syncthreads();
        }
        int c = carry_s;
        if (idx < N_NODES) {
            int ex = c + sh[t] - v;
            g_off[idx] = ex;
            g_cur[idx] = ex;
        }
        __syncthreads();
        if (t == 1023) carry_s = c + sh[1023];
        __syncthreads();
    }
    if (t == 0) g_off[N_NODES] = carry_s;
}

__global__ void k_fill(const int* __restrict__ ei) {
    int e = blockIdx.x * blockDim.x + threadIdx.x;
    if (e >= E_TOT) return;
    int s, d;
    if (e < N_EDGES) { s = ei[e]; d = ei[N_EDGES + e]; }
    else             { s = d = e - N_EDGES; }
    int pos = atomicAdd(&g_cur[d], 1);
    g_srcs[pos] = s;
}

// ----------------------------- SGEMM 128x128 tiles, BK=16 ------------------
// C[M,128] = A[M,128] @ W[128,128] + bias ; A selected by in_sel, C by out_sel
__global__ void __launch_bounds__(256) k_gemm_bias(
    int in_sel, int out_sel,
    const float* __restrict__ W, const float* __restrict__ bias, int M)
{
    const float* A = in_sel ? g_buf1 : g_buf0;
    float* C = out_sel ? g_xr : g_xl;

    __shared__ float As[16][132];   // transposed A tile: As[k][m]
    __shared__ float Bs[16][132];

    int tid = threadIdx.x;
    int m0 = blockIdx.x * 128;

    float acc[8][8];
    #pragma unroll
    for (int i = 0; i < 8; i++)
        #pragma unroll
        for (int j = 0; j < 8; j++) acc[i][j] = 0.f;

    int tm = (tid >> 4) * 8;
    int tn = (tid & 15) * 8;
    int ar = tid >> 2;
    int ac = (tid & 3) * 4;
    int brw = tid >> 5;
    int bcl = (tid & 31) * 4;

    for (int k0 = 0; k0 < D; k0 += 16) {
        #pragma unroll
        for (int rr = 0; rr < 128; rr += 64) {
            int gr = m0 + ar + rr;
            float4 v = make_float4(0.f, 0.f, 0.f, 0.f);
            if (gr < M) v = *(const float4*)(A + (size_t)gr * D + k0 + ac);
            As[ac + 0][ar + rr] = v.x;
            As[ac + 1][ar + rr] = v.y;
            As[ac + 2][ar + rr] = v.z;
            As[ac + 3][ar + rr] = v.w;
        }
        #pragma unroll
        for (int rr = 0; rr < 16; rr += 8) {
            float4 v = *(const float4*)(W + (size_t)(k0 + brw + rr) * D + bcl);
            *(float4*)&Bs[brw + rr][bcl] = v;
        }
        __syncthreads();
        #pragma unroll
        for (int k = 0; k < 16; k++) {
            float4 a0 = *(float4*)&As[k][tm];
            float4 a1 = *(float4*)&As[k][tm + 4];
            float4 b0 = *(float4*)&Bs[k][tn];
            float4 b1 = *(float4*)&Bs[k][tn + 4];
            float af[8] = {a0.x, a0.y, a0.z, a0.w, a1.x, a1.y, a1.z, a1.w};
            float bf[8] = {b0.x, b0.y, b0.z, b0.w, b1.x, b1.y, b1.z, b1.w};
            #pragma unroll
            for (int i = 0; i < 8; i++)
                #pragma unroll
                for (int j = 0; j < 8; j++)
                    acc[i][j] = fmaf(af[i], bf[j], acc[i][j]);
        }
        __syncthreads();
    }

    float4 bv0 = *(const float4*)(bias + tn);
    float4 bv1 = *(const float4*)(bias + tn + 4);
    float bb[8] = {bv0.x, bv0.y, bv0.z, bv0.w, bv1.x, bv1.y, bv1.z, bv1.w};
    #pragma unroll
    for (int i = 0; i < 8; i++) {
        int gr = m0 + tm + i;
        if (gr < M) {
            float4 o0 = make_float4(acc[i][0] + bb[0], acc[i][1] + bb[1],
                                    acc[i][2] + bb[2], acc[i][3] + bb[3]);
            float4 o1 = make_float4(acc[i][4] + bb[4], acc[i][5] + bb[5],
                                    acc[i][6] + bb[6], acc[i][7] + bb[7]);
            *(float4*)(C + (size_t)gr * D + tn) = o0;
            *(float4*)(C + (size_t)gr * D + tn + 4) = o1;
        }
    }
}

// ----------------------------- fused edge phase: warp per dst node ---------
// online segment-softmax + weighted aggregation + bias + ELU
__global__ void __launch_bounds__(256) k_aggregate(
    int out_sel, const float* __restrict__ att, const float* __restrict__ bias)
{
    int gid  = (blockIdx.x * blockDim.x + threadIdx.x) >> 5;
    int lane = threadIdx.x & 31;
    if (gid >= N_NODES) return;

    const float4* xl4 = (const float4*)g_xl;
    const float4* xr4 = (const float4*)g_xr;

    float4 xr_v = xr4[gid * 32 + lane];
    float4 a    = ((const float4*)att)[lane];

    float m = -INFINITY, s = 0.f;
    float ax = 0.f, ay = 0.f, az = 0.f, aw = 0.f;

    int beg = g_off[gid];
    int end = g_off[gid + 1];
    for (int e = beg; e < end; e++) {
        int src = g_srcs[e];
        float4 xv = xl4[src * 32 + lane];
        float tx = xv.x + xr_v.x;
        float ty = xv.y + xr_v.y;
        float tz = xv.z + xr_v.z;
        float tw = xv.w + xr_v.w;
        float p = lrelu(tx) * a.x + lrelu(ty) * a.y + lrelu(tz) * a.z + lrelu(tw) * a.w;
        // reduce over 4-lane group = one head (lanes 4h..4h+3)
        p += __shfl_xor_sync(0xffffffffu, p, 1);
        p += __shfl_xor_sync(0xffffffffu, p, 2);
        // online softmax update
        float mn = fmaxf(m, p);
        float sc = __expf(m - mn);     // 0 on first edge (m = -inf)
        float w  = __expf(p - mn);
        s  = s * sc + w;
        ax = ax * sc + xv.x * w;
        ay = ay * sc + xv.y * w;
        az = az * sc + xv.z * w;
        aw = aw * sc + xv.w * w;
        m = mn;
    }
    float inv = 1.f / s;               // >=1 edge guaranteed (self loop)
    float4 bv = ((const float4*)bias)[lane];
    float4 o;
    o.x = elu(ax * inv + bv.x);
    o.y = elu(ay * inv + bv.y);
    o.z = elu(az * inv + bv.z);
    o.w = elu(aw * inv + bv.w);
    float* hout = out_sel ? g_buf1 : g_buf0;
    ((float4*)hout)[gid * 32 + lane] = o;
}

// ----------------------------- pooling + classifier ------------------------
__global__ void k_pool(int sel, const int* __restrict__ batch) {
    int id = blockIdx.x * blockDim.x + threadIdx.x;
    if (id >= N_NODES * 32) return;
    int node = id >> 5, lane = id & 31;
    int g = batch[node];
    const float4* h4 = (const float4*)(sel ? g_buf1 : g_buf0);
    float4 v = h4[node * 32 + lane];
    atomicAdd(&g_psum[g * D + lane * 4 + 0], v.x);
    atomicAdd(&g_psum[g * D + lane * 4 + 1], v.y);
    atomicAdd(&g_psum[g * D + lane * 4 + 2], v.z);
    atomicAdd(&g_psum[g * D + lane * 4 + 3], v.w);
    if (lane == 0) atomicAdd(&g_pcnt[g], 1);
}

__global__ void k_head(const float* __restrict__ Wout, const float* __restrict__ bout,
                       float* __restrict__ out) {
    int g = threadIdx.x;
    if (g >= N_GRAPHS) return;
    float inv = 1.f / fmaxf((float)g_pcnt[g], 1.f);
    float lg[N_CLASSES];
    #pragma unroll
    for (int c = 0; c < N_CLASSES; c++) lg[c] = bout[c];
    for (int d = 0; d < D; d++) {
        float pv = g_psum[g * D + d] * inv;
        #pragma unroll
        for (int c = 0; c < N_CLASSES; c++)
            lg[c] = fmaf(pv, Wout[d * N_CLASSES + c], lg[c]);
    }
    float mx = lg[0];
    #pragma unroll
    for (int c = 1; c < N_CLASSES; c++) mx = fmaxf(mx, lg[c]);
    float sum = 0.f;
    #pragma unroll
    for (int c = 0; c < N_CLASSES; c++) sum += expf(lg[c] - mx);
    float ls = logf(sum);
    #pragma unroll
    for (int c = 0; c < N_CLASSES; c++) out[g * N_CLASSES + c] = lg[c] - mx - ls;
}

// ----------------------------- launch --------------------------------------
extern "C" void kernel_launch(void* const* d_in, const int* in_sizes, int n_in,
                              void* d_out, int out_size) {
    const float* x    = (const float*)d_in[0];
    const int*   ei   = (const int*)d_in[1];
    const int*   batch= (const int*)d_in[2];
    const float* Wl   = (const float*)d_in[3];
    const float* bl   = (const float*)d_in[4];
    const float* Wr   = (const float*)d_in[5];
    const float* brp  = (const float*)d_in[6];
    const float* att  = (const float*)d_in[7];
    const float* bias = (const float*)d_in[8];
    const float* Wout = (const float*)d_in[9];
    const float* bout = (const float*)d_in[10];
    float* out = (float*)d_out;

    // init + CSR build (per replay; same edges for all 5 layers)
    k_init<<<(N_NODES * D / 4 + 255) / 256, 256>>>(x);
    k_count<<<(N_EDGES + 255) / 256, 256>>>(ei);
    k_scan<<<1, 1024>>>();
    k_fill<<<(E_TOT + 255) / 256, 256>>>(ei);

    const int gemm_blocks = (N_NODES + 127) / 128;   // 391
    const int agg_blocks  = (N_NODES * 32 + 255) / 256;

    for (int l = 0; l < 5; l++) {
        int in_sel  = l & 1;
        int out_sel = (l + 1) & 1;
        k_gemm_bias<<<gemm_blocks, 256>>>(in_sel, 0, Wl + l * D * D, bl + l * D, N_NODES);
        k_gemm_bias<<<gemm_blocks, 256>>>(in_sel, 1, Wr + l * D * D, brp + l * D, N_NODES);
        k_aggregate<<<agg_blocks, 256>>>(out_sel, att + l * D, bias + l * D);
    }

    k_pool<<<(N_NODES * 32 + 255) / 256, 256>>>(1, batch);   // layer-5 output lives in g_buf1
    k_head<<<1, 64>>>(Wout, bout, out);
}

// round 4
// speedup vs baseline: 1.1306x; 1.1306x over previous
#include <cuda_runtime.h>
#include <cuda_bf16.h>
#include <math.h>
#include <stdint.h>

#define N_NODES  50000
#define N_EDGES  800000
#define E_TOT    850000
#define N_GRAPHS 64
#define D        128
#define N_CLASSES 10
#define NEG_SLOPE 0.2f
#define N_LAYERS 5

// ----------------------------- scratch (device globals) --------------------
__device__ float g_h [N_NODES * D];
__device__ float g_xl[N_NODES * D];
__device__ float g_xr[N_NODES * D];
__device__ __nv_bfloat16 g_in_hi[N_NODES * D];
__device__ __nv_bfloat16 g_in_lo[N_NODES * D];
__device__ __nv_bfloat16 g_wt_hi[N_LAYERS * 2 * D * D];  // W^T [l2][n][k]
__device__ __nv_bfloat16 g_wt_lo[N_LAYERS * 2 * D * D];
__device__ int   g_deg[N_NODES];
__device__ int   g_off[N_NODES + 1];
__device__ int   g_cur[N_NODES];
__device__ int   g_srcs[E_TOT];
__device__ float g_psum[N_GRAPHS * D];
__device__ int   g_pcnt[N_GRAPHS];

__device__ __forceinline__ float lrelu(float v) { return v > 0.f ? v : NEG_SLOPE * v; }
__device__ __forceinline__ float elu(float v)   { return v > 0.f ? v : __expf(v) - 1.f; }

__device__ __forceinline__ uint32_t smem_u32(const void* p) {
    uint32_t a;
    asm("{ .reg .u64 t; cvta.to.shared.u64 t, %1; cvt.u32.u64 %0, t; }" : "=r"(a) : "l"(p));
    return a;
}

#define LDSM_X4(R, addr) \
    asm volatile("ldmatrix.sync.aligned.m8n8.x4.shared.b16 {%0,%1,%2,%3}, [%4];" \
        : "=r"((R)[0]), "=r"((R)[1]), "=r"((R)[2]), "=r"((R)[3]) : "r"(addr))
#define LDSM_X2(R0, R1, addr) \
    asm volatile("ldmatrix.sync.aligned.m8n8.x2.shared.b16 {%0,%1}, [%2];" \
        : "=r"(R0), "=r"(R1) : "r"(addr))
#define MMA_BF16(C, A, B0, B1) \
    asm volatile("mma.sync.aligned.m16n8k16.row.col.f32.bf16.bf16.f32 " \
        "{%0,%1,%2,%3}, {%4,%5,%6,%7}, {%8,%9}, {%0,%1,%2,%3};" \
        : "+f"((C)[0]), "+f"((C)[1]), "+f"((C)[2]), "+f"((C)[3]) \
        : "r"((A)[0]), "r"((A)[1]), "r"((A)[2]), "r"((A)[3]), "r"(B0), "r"(B1))

// ----------------------------- init / prep ---------------------------------
__global__ void k_init() {
    int i = blockIdx.x * blockDim.x + threadIdx.x;
    if (i < N_NODES) g_deg[i] = 1;
    if (i < N_GRAPHS * D) g_psum[i] = 0.f;
    if (i < N_GRAPHS) g_pcnt[i] = 0;
}

__global__ void k_prep_x(const float* __restrict__ x) {
    int i = blockIdx.x * blockDim.x + threadIdx.x;
    if (i >= N_NODES * D / 4) return;
    float4 v = ((const float4*)x)[i];
    __nv_bfloat16 h[4], l[4];
    float vv[4] = {v.x, v.y, v.z, v.w};
    #pragma unroll
    for (int j = 0; j < 4; j++) {
        h[j] = __float2bfloat16(vv[j]);
        l[j] = __float2bfloat16(vv[j] - __bfloat162float(h[j]));
    }
    ((uint2*)g_in_hi)[i] = *(const uint2*)h;
    ((uint2*)g_in_lo)[i] = *(const uint2*)l;
}

__global__ void k_prep_w(const float* __restrict__ Wl, const float* __restrict__ Wr) {
    int tid = blockIdx.x * blockDim.x + threadIdx.x;
    if (tid >= N_LAYERS * 2 * D * 32) return;
    int l2  = tid / (D * 32);
    int rem = tid % (D * 32);
    int n = rem / 32;
    int k0 = (rem % 32) * 4;
    const float* W = ((l2 & 1) ? Wr : Wl) + (l2 >> 1) * D * D;
    __nv_bfloat16 h[4], l[4];
    #pragma unroll
    for (int j = 0; j < 4; j++) {
        float v = W[(k0 + j) * D + n];
        h[j] = __float2bfloat16(v);
        l[j] = __float2bfloat16(v - __bfloat162float(h[j]));
    }
    int oi = (l2 * D + n) * D + k0;
    *(uint2*)(g_wt_hi + oi) = *(const uint2*)h;
    *(uint2*)(g_wt_lo + oi) = *(const uint2*)l;
}

// ----------------------------- CSR build -----------------------------------
__global__ void k_count(const int* __restrict__ ei) {
    int e = blockIdx.x * blockDim.x + threadIdx.x;
    if (e < N_EDGES) atomicAdd(&g_deg[ei[N_EDGES + e]], 1);
}

__global__ void k_scan() {
    __shared__ int sh[1024];
    const int CH = (N_NODES + 1023) / 1024;
    int t = threadIdx.x;
    int beg = t * CH, end = min(beg + CH, N_NODES);
    int s = 0;
    for (int i = beg; i < end; i++) s += g_deg[i];
    sh[t] = s;
    __syncthreads();
    #pragma unroll
    for (int off = 1; off < 1024; off <<= 1) {
        int add = (t >= off) ? sh[t - off] : 0;
        __syncthreads();
        sh[t] += add;
        __syncthreads();
    }
    int run = sh[t] - s;
    for (int i = beg; i < end; i++) {
        g_off[i] = run; g_cur[i] = run;
        run += g_deg[i];
    }
    if (t == 1023) g_off[N_NODES] = run;
}

__global__ void k_fill(const int* __restrict__ ei) {
    int e = blockIdx.x * blockDim.x + threadIdx.x;
    if (e >= E_TOT) return;
    int s, d;
    if (e < N_EDGES) { s = ei[e]; d = ei[N_EDGES + e]; }
    else             { s = d = e - N_EDGES; }
    int pos = atomicAdd(&g_cur[d], 1);
    g_srcs[pos] = s;
}

// ----------------------------- mma.sync bf16-split GEMM --------------------
// blockIdx.y: 0 -> xl = A@Wl + bl ; 1 -> xr = A@Wr + br
// SMEM tiles: 128 rows x 128 bf16, row stride 272B (conflict-free ldmatrix).
#define TSTRIDE 272
#define TBYTES  (128 * TSTRIDE)          // 34816
#define GSM_TOTAL (4 * TBYTES)           // 139264

__global__ void __launch_bounds__(256, 1) k_gemm_mma(
    int layer, const float* __restrict__ bl, const float* __restrict__ br)
{
    extern __shared__ char smem[];
    const int tid = threadIdx.x, wid = tid >> 5, lane = tid & 31;
    const int m0 = blockIdx.x * 128;
    const int which = blockIdx.y;

    // ---- stage tiles ----
    const uint4* ahi4 = (const uint4*)g_in_hi;
    const uint4* alo4 = (const uint4*)g_in_lo;
    for (int c = tid; c < 2048; c += 256) {
        int row = c >> 4, cb = c & 15;
        int gr = m0 + row;
        uint4 vh = make_uint4(0, 0, 0, 0), vl = make_uint4(0, 0, 0, 0);
        if (gr < N_NODES) { vh = ahi4[gr * 16 + cb]; vl = alo4[gr * 16 + cb]; }
        *(uint4*)(smem + row * TSTRIDE + cb * 16) = vh;
        *(uint4*)(smem + TBYTES + row * TSTRIDE + cb * 16) = vl;
    }
    const uint4* whsrc = (const uint4*)g_wt_hi + (layer * 2 + which) * 2048;
    const uint4* wlsrc = (const uint4*)g_wt_lo + (layer * 2 + which) * 2048;
    for (int c = tid; c < 2048; c += 256) {
        int row = c >> 4, cb = c & 15;
        *(uint4*)(smem + 2 * TBYTES + row * TSTRIDE + cb * 16) = whsrc[c];
        *(uint4*)(smem + 3 * TBYTES + row * TSTRIDE + cb * 16) = wlsrc[c];
    }
    __syncthreads();

    uint32_t sb = smem_u32(smem);
    uint32_t Ahi = sb, Alo = sb + TBYTES, Whi = sb + 2 * TBYTES, Wlo = sb + 3 * TBYTES;

    float acc[16][4];
    #pragma unroll
    for (int j = 0; j < 16; j++)
        #pragma unroll
        for (int q = 0; q < 4; q++) acc[j][q] = 0.f;

    // ldmatrix lane addressing
    const int wrow = wid * 16;
    uint32_t a_off = (uint32_t)((wrow + (lane & 7) + ((lane >> 3) & 1) * 8) * TSTRIDE
                                + (lane >> 4) * 16);
    uint32_t b_off = (uint32_t)((lane & 7) * TSTRIDE + ((lane >> 3) & 1) * 16);

    #pragma unroll
    for (int k0 = 0; k0 < 8; k0++) {
        uint32_t ah[4], al[4];
        LDSM_X4(ah, Ahi + a_off + k0 * 32);
        LDSM_X4(al, Alo + a_off + k0 * 32);
        #pragma unroll
        for (int j = 0; j < 16; j++) {
            uint32_t bh0, bh1, bl0, bl1;
            LDSM_X2(bh0, bh1, Whi + b_off + j * (8 * TSTRIDE) + k0 * 32);
            LDSM_X2(bl0, bl1, Wlo + b_off + j * (8 * TSTRIDE) + k0 * 32);
            MMA_BF16(acc[j], ah, bh0, bh1);
            MMA_BF16(acc[j], ah, bl0, bl1);
            MMA_BF16(acc[j], al, bh0, bh1);
        }
    }

    // ---- epilogue: bias + store fp32 ----
    const float* bias = which ? br : bl;
    float* outp = which ? g_xr : g_xl;
    int r = lane >> 2, c2 = (lane & 3) * 2;
    int row0 = m0 + wrow + r, row1 = row0 + 8;
    #pragma unroll
    for (int j = 0; j < 16; j++) {
        int col = j * 8 + c2;
        float b0v = bias[col], b1v = bias[col + 1];
        if (row0 < N_NODES)
            *(float2*)(outp + (size_t)row0 * D + col) = make_float2(acc[j][0] + b0v, acc[j][1] + b1v);
        if (row1 < N_NODES)
            *(float2*)(outp + (size_t)row1 * D + col) = make_float2(acc[j][2] + b0v, acc[j][3] + b1v);
    }
}

// ----------------------------- fused edge phase ----------------------------
__global__ void __launch_bounds__(256) k_aggregate(
    const float* __restrict__ att, const float* __restrict__ bias)
{
    int gid  = (blockIdx.x * blockDim.x + threadIdx.x) >> 5;
    int lane = threadIdx.x & 31;
    if (gid >= N_NODES) return;

    const float4* xl4 = (const float4*)g_xl;
    const float4* xr4 = (const float4*)g_xr;

    float4 xr_v = xr4[gid * 32 + lane];
    float4 a    = ((const float4*)att)[lane];

    float m = -INFINITY, s = 0.f;
    float ax = 0.f, ay = 0.f, az = 0.f, aw = 0.f;

    int beg = g_off[gid];
    int end = g_off[gid + 1];
    for (int e = beg; e < end; e++) {
        int src = g_srcs[e];
        float4 xv = xl4[src * 32 + lane];
        float p = lrelu(xv.x + xr_v.x) * a.x + lrelu(xv.y + xr_v.y) * a.y +
                  lrelu(xv.z + xr_v.z) * a.z + lrelu(xv.w + xr_v.w) * a.w;
        p += __shfl_xor_sync(0xffffffffu, p, 1);
        p += __shfl_xor_sync(0xffffffffu, p, 2);
        float mn = fmaxf(m, p);
        float sc = __expf(m - mn);
        float w  = __expf(p - mn);
        s  = s * sc + w;
        ax = ax * sc + xv.x * w;
        ay = ay * sc + xv.y * w;
        az = az * sc + xv.z * w;
        aw = aw * sc + xv.w * w;
        m = mn;
    }
    float inv = 1.f / s;
    float4 bv = ((const float4*)bias)[lane];
    float4 o;
    o.x = elu(ax * inv + bv.x);
    o.y = elu(ay * inv + bv.y);
    o.z = elu(az * inv + bv.z);
    o.w = elu(aw * inv + bv.w);
    ((float4*)g_h)[gid * 32 + lane] = o;

    __nv_bfloat16 h[4], l[4];
    float vv[4] = {o.x, o.y, o.z, o.w};
    #pragma unroll
    for (int j = 0; j < 4; j++) {
        h[j] = __float2bfloat16(vv[j]);
        l[j] = __float2bfloat16(vv[j] - __bfloat162float(h[j]));
    }
    ((uint2*)g_in_hi)[gid * 32 + lane] = *(const uint2*)h;
    ((uint2*)g_in_lo)[gid * 32 + lane] = *(const uint2*)l;
}

// ----------------------------- pooling + classifier ------------------------
__global__ void k_pool(const int* __restrict__ batch) {
    int id = blockIdx.x * blockDim.x + threadIdx.x;
    if (id >= N_NODES * 32) return;
    int node = id >> 5, lane = id & 31;
    int g = batch[node];
    float4 v = ((const float4*)g_h)[node * 32 + lane];
    atomicAdd(&g_psum[g * D + lane * 4 + 0], v.x);
    atomicAdd(&g_psum[g * D + lane * 4 + 1], v.y);
    atomicAdd(&g_psum[g * D + lane * 4 + 2], v.z);
    atomicAdd(&g_psum[g * D + lane * 4 + 3], v.w);
    if (lane == 0) atomicAdd(&g_pcnt[g], 1);
}

__global__ void k_head(const float* __restrict__ Wout, const float* __restrict__ bout,
                       float* __restrict__ out) {
    int g = threadIdx.x;
    if (g >= N_GRAPHS) return;
    float inv = 1.f / fmaxf((float)g_pcnt[g], 1.f);
    float lg[N_CLASSES];
    #pragma unroll
    for (int c = 0; c < N_CLASSES; c++) lg[c] = bout[c];
    for (int d = 0; d < D; d++) {
        float pv = g_psum[g * D + d] * inv;
        #pragma unroll
        for (int c = 0; c < N_CLASSES; c++)
            lg[c] = fmaf(pv, Wout[d * N_CLASSES + c], lg[c]);
    }
    float mx = lg[0];
    #pragma unroll
    for (int c = 1; c < N_CLASSES; c++) mx = fmaxf(mx, lg[c]);
    float sum = 0.f;
    #pragma unroll
    for (int c = 0; c < N_CLASSES; c++) sum += expf(lg[c] - mx);
    float ls = logf(sum);
    #pragma unroll
    for (int c = 0; c < N_CLASSES; c++) out[g * N_CLASSES + c] = lg[c] - mx - ls;
}

// ----------------------------- launch --------------------------------------
extern "C" void kernel_launch(void* const* d_in, const int* in_sizes, int n_in,
                              void* d_out, int out_size) {
    const float* x    = (const float*)d_in[0];
    const int*   ei   = (const int*)d_in[1];
    const int*   batch= (const int*)d_in[2];
    const float* Wl   = (const float*)d_in[3];
    const float* bl   = (const float*)d_in[4];
    const float* Wr   = (const float*)d_in[5];
    const float* brp  = (const float*)d_in[6];
    const float* att  = (const float*)d_in[7];
    const float* bias = (const float*)d_in[8];
    const float* Wout = (const float*)d_in[9];
    const float* bout = (const float*)d_in[10];
    float* out = (float*)d_out;

    cudaFuncSetAttribute(k_gemm_mma, cudaFuncAttributeMaxDynamicSharedMemorySize, GSM_TOTAL);

    k_init<<<(N_NODES + 255) / 256, 256>>>();
    k_prep_x<<<(N_NODES * D / 4 + 255) / 256, 256>>>(x);
    k_prep_w<<<(N_LAYERS * 2 * D * 32 + 255) / 256, 256>>>(Wl, Wr);
    k_count<<<(N_EDGES + 255) / 256, 256>>>(ei);
    k_scan<<<1, 1024>>>();
    k_fill<<<(E_TOT + 255) / 256, 256>>>(ei);

    dim3 gemm_grid((N_NODES + 127) / 128, 2);             // 391 x 2
    const int agg_blocks = (N_NODES * 32 + 255) / 256;    // 6250

    for (int l = 0; l < N_LAYERS; l++) {
        k_gemm_mma<<<gemm_grid, 256, GSM_TOTAL>>>(l, bl + l * D, brp + l * D);
        k_aggregate<<<agg_blocks, 256>>>(att + l * D, bias + l * D);
    }

    k_pool<<<(N_NODES * 32 + 255) / 256, 256>>>(batch);
    k_head<<<1, 64>>>(Wout, bout, out);
}

// round 5
// speedup vs baseline: 1.1525x; 1.0194x over previous
#include <cuda_runtime.h>
#include <cuda_bf16.h>
#include <cuda_fp16.h>
#include <math.h>
#include <stdint.h>

#define N_NODES  50000
#define N_EDGES  800000
#define E_TOT    850000
#define N_GRAPHS 64
#define D        128
#define N_CLASSES 10
#define NEG_SLOPE 0.2f
#define N_LAYERS 5

// ----------------------------- scratch (device globals) --------------------
__device__ float  g_h   [N_NODES * D];
__device__ __half g_xl_h[N_NODES * D];      // fp16 xl (gather stream)
__device__ float  g_xr  [N_NODES * D];
__device__ __nv_bfloat16 g_in_hi[N_NODES * D];
__device__ __nv_bfloat16 g_in_lo[N_NODES * D];
__device__ __nv_bfloat16 g_wt_hi[N_LAYERS * 2 * D * D];  // W^T [l2][n][k]
__device__ __nv_bfloat16 g_wt_lo[N_LAYERS * 2 * D * D];
__device__ int   g_deg[N_NODES];            // zero-init at load; scan resets to 0
__device__ int   g_off[N_NODES + 1];
__device__ int   g_cur[N_NODES];
__device__ int   g_srcs[E_TOT];
__device__ float g_psum[N_GRAPHS * D];
__device__ int   g_pcnt[N_GRAPHS];

__device__ __forceinline__ float lrelu(float v) { return v > 0.f ? v : NEG_SLOPE * v; }
__device__ __forceinline__ float elu(float v)   { return v > 0.f ? v : __expf(v) - 1.f; }

__device__ __forceinline__ uint32_t smem_u32(const void* p) {
    uint32_t a;
    asm("{ .reg .u64 t; cvta.to.shared.u64 t, %1; cvt.u32.u64 %0, t; }" : "=r"(a) : "l"(p));
    return a;
}

#define LDSM_X4(R, addr) \
    asm volatile("ldmatrix.sync.aligned.m8n8.x4.shared.b16 {%0,%1,%2,%3}, [%4];" \
        : "=r"((R)[0]), "=r"((R)[1]), "=r"((R)[2]), "=r"((R)[3]) : "r"(addr))
#define MMA_BF16(C, A, B0, B1) \
    asm volatile("mma.sync.aligned.m16n8k16.row.col.f32.bf16.bf16.f32 " \
        "{%0,%1,%2,%3}, {%4,%5,%6,%7}, {%8,%9}, {%0,%1,%2,%3};" \
        : "+f"((C)[0]), "+f"((C)[1]), "+f"((C)[2]), "+f"((C)[3]) \
        : "r"((A)[0]), "r"((A)[1]), "r"((A)[2]), "r"((A)[3]), "r"(B0), "r"(B1))

// ----------------------------- fused prep -----------------------------------
// roles by global index; g_deg enters zeroed (module-load zero-init, and k_scan
// re-zeroes it each replay), so counting starts immediately.
__global__ void k_prep(const float* __restrict__ x, const int* __restrict__ ei,
                       const float* __restrict__ Wl, const float* __restrict__ Wr) {
    int i = blockIdx.x * blockDim.x + threadIdx.x;

    if (i < N_NODES * D / 4) {               // bf16-split of input x
        float4 v = ((const float4*)x)[i];
        __nv_bfloat16 h[4], l[4];
        float vv[4] = {v.x, v.y, v.z, v.w};
        #pragma unroll
        for (int j = 0; j < 4; j++) {
            h[j] = __float2bfloat16(vv[j]);
            l[j] = __float2bfloat16(vv[j] - __bfloat162float(h[j]));
        }
        ((uint2*)g_in_hi)[i] = *(const uint2*)h;
        ((uint2*)g_in_lo)[i] = *(const uint2*)l;
    }
    if (i < N_EDGES) atomicAdd(&g_deg[ei[N_EDGES + i]], 1);
    if (i < N_LAYERS * 2 * D * 32) {         // W^T bf16 split
        int l2  = i / (D * 32);
        int rem = i % (D * 32);
        int n = rem / 32;
        int k0 = (rem % 32) * 4;
        const float* W = ((l2 & 1) ? Wr : Wl) + (l2 >> 1) * D * D;
        __nv_bfloat16 h[4], l[4];
        #pragma unroll
        for (int j = 0; j < 4; j++) {
            float v = W[(k0 + j) * D + n];
            h[j] = __float2bfloat16(v);
            l[j] = __float2bfloat16(v - __bfloat162float(h[j]));
        }
        int oi = (l2 * D + n) * D + k0;
        *(uint2*)(g_wt_hi + oi) = *(const uint2*)h;
        *(uint2*)(g_wt_lo + oi) = *(const uint2*)l;
    }
    if (i < N_GRAPHS * D) g_psum[i] = 0.f;
    if (i < N_GRAPHS) g_pcnt[i] = 0;
}

// single-block scan; degree = g_deg + 1 (self loop); resets g_deg for next replay
__global__ void k_scan() {
    __shared__ int sh[1024];
    const int CH = (N_NODES + 1023) / 1024;
    int t = threadIdx.x;
    int beg = t * CH, end = min(beg + CH, N_NODES);
    int s = 0;
    for (int i = beg; i < end; i++) s += g_deg[i] + 1;
    sh[t] = s;
    __syncthreads();
    #pragma unroll
    for (int off = 1; off < 1024; off <<= 1) {
        int add = (t >= off) ? sh[t - off] : 0;
        __syncthreads();
        sh[t] += add;
        __syncthreads();
    }
    int run = sh[t] - s;
    for (int i = beg; i < end; i++) {
        g_off[i] = run; g_cur[i] = run;
        run += g_deg[i] + 1;
        g_deg[i] = 0;                        // ready for next replay
    }
    if (t == 1023) g_off[N_NODES] = run;
}

__global__ void k_fill(const int* __restrict__ ei) {
    int e = blockIdx.x * blockDim.x + threadIdx.x;
    if (e >= E_TOT) return;
    int s, d;
    if (e < N_EDGES) { s = ei[e]; d = ei[N_EDGES + e]; }
    else             { s = d = e - N_EDGES; }
    int pos = atomicAdd(&g_cur[d], 1);
    g_srcs[pos] = s;
}

// ----------------------------- mma.sync bf16-split GEMM --------------------
// blockIdx.y: 0 -> xl (fp16 out) ; 1 -> xr (fp32 out)
#define TSTRIDE 272
#define TBYTES  (128 * TSTRIDE)
#define GSM_TOTAL (4 * TBYTES)

__global__ void __launch_bounds__(256, 1) k_gemm_mma(
    int layer, const float* __restrict__ bl, const float* __restrict__ br)
{
    extern __shared__ char smem[];
    const int tid = threadIdx.x, wid = tid >> 5, lane = tid & 31;
    const int m0 = blockIdx.x * 128;
    const int which = blockIdx.y;

    const uint4* ahi4 = (const uint4*)g_in_hi;
    const uint4* alo4 = (const uint4*)g_in_lo;
    for (int c = tid; c < 2048; c += 256) {
        int row = c >> 4, cb = c & 15;
        int gr = m0 + row;
        uint4 vh = make_uint4(0, 0, 0, 0), vl = make_uint4(0, 0, 0, 0);
        if (gr < N_NODES) { vh = ahi4[gr * 16 + cb]; vl = alo4[gr * 16 + cb]; }
        *(uint4*)(smem + row * TSTRIDE + cb * 16) = vh;
        *(uint4*)(smem + TBYTES + row * TSTRIDE + cb * 16) = vl;
    }
    const uint4* whsrc = (const uint4*)g_wt_hi + (layer * 2 + which) * 2048;
    const uint4* wlsrc = (const uint4*)g_wt_lo + (layer * 2 + which) * 2048;
    for (int c = tid; c < 2048; c += 256) {
        int row = c >> 4, cb = c & 15;
        *(uint4*)(smem + 2 * TBYTES + row * TSTRIDE + cb * 16) = whsrc[c];
        *(uint4*)(smem + 3 * TBYTES + row * TSTRIDE + cb * 16) = wlsrc[c];
    }
    __syncthreads();

    uint32_t sb = smem_u32(smem);
    uint32_t Ahi = sb, Alo = sb + TBYTES, Whi = sb + 2 * TBYTES, Wlo = sb + 3 * TBYTES;

    float acc[16][4];
    #pragma unroll
    for (int j = 0; j < 16; j++)
        #pragma unroll
        for (int q = 0; q < 4; q++) acc[j][q] = 0.f;

    const int wrow = wid * 16;
    uint32_t a_off = (uint32_t)((wrow + (lane & 7) + ((lane >> 3) & 1) * 8) * TSTRIDE
                                + (lane >> 4) * 16);
    // x4 B addressing: matrices {j rows, k-lo16B}, {j, k-hi}, {j+8, k-lo}, {j+8, k-hi}
    uint32_t b_off4 = (uint32_t)((lane & 7) * TSTRIDE + ((lane >> 3) & 1) * 16
                                 + (lane >> 4) * (8 * TSTRIDE));

    #pragma unroll
    for (int k0 = 0; k0 < 8; k0++) {
        uint32_t ah[4], al[4];
        LDSM_X4(ah, Ahi + a_off + k0 * 32);
        LDSM_X4(al, Alo + a_off + k0 * 32);
        #pragma unroll
        for (int jp = 0; jp < 8; jp++) {
            uint32_t bh[4], blo[4];
            LDSM_X4(bh,  Whi + b_off4 + jp * (16 * TSTRIDE) + k0 * 32);
            LDSM_X4(blo, Wlo + b_off4 + jp * (16 * TSTRIDE) + k0 * 32);
            MMA_BF16(acc[2 * jp],     ah, bh[0],  bh[1]);
            MMA_BF16(acc[2 * jp + 1], ah, bh[2],  bh[3]);
            MMA_BF16(acc[2 * jp],     ah, blo[0], blo[1]);
            MMA_BF16(acc[2 * jp + 1], ah, blo[2], blo[3]);
            MMA_BF16(acc[2 * jp],     al, bh[0],  bh[1]);
            MMA_BF16(acc[2 * jp + 1], al, bh[2],  bh[3]);
        }
    }

    const float* bias = which ? br : bl;
    int r = lane >> 2, c2 = (lane & 3) * 2;
    int row0 = m0 + wrow + r, row1 = row0 + 8;
    if (which == 0) {                        // fp16 xl
        #pragma unroll
        for (int j = 0; j < 16; j++) {
            int col = j * 8 + c2;
            float b0v = bias[col], b1v = bias[col + 1];
            if (row0 < N_NODES)
                *(__half2*)(g_xl_h + (size_t)row0 * D + col) =
                    __floats2half2_rn(acc[j][0] + b0v, acc[j][1] + b1v);
            if (row1 < N_NODES)
                *(__half2*)(g_xl_h + (size_t)row1 * D + col) =
                    __floats2half2_rn(acc[j][2] + b0v, acc[j][3] + b1v);
        }
    } else {                                 // fp32 xr
        #pragma unroll
        for (int j = 0; j < 16; j++) {
            int col = j * 8 + c2;
            float b0v = bias[col], b1v = bias[col + 1];
            if (row0 < N_NODES)
                *(float2*)(g_xr + (size_t)row0 * D + col) = make_float2(acc[j][0] + b0v, acc[j][1] + b1v);
            if (row1 < N_NODES)
                *(float2*)(g_xr + (size_t)row1 * D + col) = make_float2(acc[j][2] + b0v, acc[j][3] + b1v);
        }
    }
}

// ----------------------------- fused edge phase (fp16 gather, pair unroll) --
__device__ __forceinline__ float4 h4_to_f4(uint2 u) {
    float2 a = __half22float2(*(__half2*)&u.x);
    float2 b = __half22float2(*(__half2*)&u.y);
    return make_float4(a.x, a.y, b.x, b.y);
}

__global__ void __launch_bounds__(256) k_aggregate(
    const float* __restrict__ att, const float* __restrict__ bias)
{
    int gid  = (blockIdx.x * blockDim.x + threadIdx.x) >> 5;
    int lane = threadIdx.x & 31;
    if (gid >= N_NODES) return;

    const uint2* xl2 = (const uint2*)g_xl_h;     // 4 halves per lane per node
    float4 xr_v = ((const float4*)g_xr)[gid * 32 + lane];
    float4 a    = ((const float4*)att)[lane];

    float m = -INFINITY, s = 0.f;
    float ax = 0.f, ay = 0.f, az = 0.f, aw = 0.f;

    int e   = g_off[gid];
    int end = g_off[gid + 1];

    for (; e + 1 < end; e += 2) {
        int s0 = g_srcs[e], s1 = g_srcs[e + 1];
        float4 x0 = h4_to_f4(xl2[(size_t)s0 * 32 + lane]);
        float4 x1 = h4_to_f4(xl2[(size_t)s1 * 32 + lane]);
        float p0 = lrelu(x0.x + xr_v.x) * a.x + lrelu(x0.y + xr_v.y) * a.y +
                   lrelu(x0.z + xr_v.z) * a.z + lrelu(x0.w + xr_v.w) * a.w;
        float p1 = lrelu(x1.x + xr_v.x) * a.x + lrelu(x1.y + xr_v.y) * a.y +
                   lrelu(x1.z + xr_v.z) * a.z + lrelu(x1.w + xr_v.w) * a.w;
        p0 += __shfl_xor_sync(0xffffffffu, p0, 1);
        p1 += __shfl_xor_sync(0xffffffffu, p1, 1);
        p0 += __shfl_xor_sync(0xffffffffu, p0, 2);
        p1 += __shfl_xor_sync(0xffffffffu, p1, 2);
        float mn = fmaxf(m, fmaxf(p0, p1));
        float sc = __expf(m - mn);
        float w0 = __expf(p0 - mn);
        float w1 = __expf(p1 - mn);
        s  = s * sc + w0 + w1;
        ax = ax * sc + x0.x * w0 + x1.x * w1;
        ay = ay * sc + x0.y * w0 + x1.y * w1;
        az = az * sc + x0.z * w0 + x1.z * w1;
        aw = aw * sc + x0.w * w0 + x1.w * w1;
        m = mn;
    }
    if (e < end) {                               // tail edge
        int s0 = g_srcs[e];
        float4 x0 = h4_to_f4(xl2[(size_t)s0 * 32 + lane]);
        float p0 = lrelu(x0.x + xr_v.x) * a.x + lrelu(x0.y + xr_v.y) * a.y +
                   lrelu(x0.z + xr_v.z) * a.z + lrelu(x0.w + xr_v.w) * a.w;
        p0 += __shfl_xor_sync(0xffffffffu, p0, 1);
        p0 += __shfl_xor_sync(0xffffffffu, p0, 2);
        float mn = fmaxf(m, p0);
        float sc = __expf(m - mn);
        float w0 = __expf(p0 - mn);
        s  = s * sc + w0;
        ax = ax * sc + x0.x * w0;
        ay = ay * sc + x0.y * w0;
        az = az * sc + x0.z * w0;
        aw = aw * sc + x0.w * w0;
    }

    float inv = 1.f / s;
    float4 bv = ((const float4*)bias)[lane];
    float4 o;
    o.x = elu(ax * inv + bv.x);
    o.y = elu(ay * inv + bv.y);
    o.z = elu(az * inv + bv.z);
    o.w = elu(aw * inv + bv.w);
    ((float4*)g_h)[gid * 32 + lane] = o;

    __nv_bfloat16 h[4], l[4];
    float vv[4] = {o.x, o.y, o.z, o.w};
    #pragma unroll
    for (int j = 0; j < 4; j++) {
        h[j] = __float2bfloat16(vv[j]);
        l[j] = __float2bfloat16(vv[j] - __bfloat162float(h[j]));
    }
    ((uint2*)g_in_hi)[gid * 32 + lane] = *(const uint2*)h;
    ((uint2*)g_in_lo)[gid * 32 + lane] = *(const uint2*)l;
}

// ----------------------------- pooling + classifier ------------------------
__global__ void k_pool(const int* __restrict__ batch) {
    int id = blockIdx.x * blockDim.x + threadIdx.x;
    if (id >= N_NODES * 32) return;
    int node = id >> 5, lane = id & 31;
    int g = batch[node];
    float4 v = ((const float4*)g_h)[node * 32 + lane];
    atomicAdd(&g_psum[g * D + lane * 4 + 0], v.x);
    atomicAdd(&g_psum[g * D + lane * 4 + 1], v.y);
    atomicAdd(&g_psum[g * D + lane * 4 + 2], v.z);
    atomicAdd(&g_psum[g * D + lane * 4 + 3], v.w);
    if (lane == 0) atomicAdd(&g_pcnt[g], 1);
}

__global__ void k_head(const float* __restrict__ Wout, const float* __restrict__ bout,
                       float* __restrict__ out) {
    int g = threadIdx.x;
    if (g >= N_GRAPHS) return;
    float inv = 1.f / fmaxf((float)g_pcnt[g], 1.f);
    float lg[N_CLASSES];
    #pragma unroll
    for (int c = 0; c < N_CLASSES; c++) lg[c] = bout[c];
    for (int d = 0; d < D; d++) {
        float pv = g_psum[g * D + d] * inv;
        #pragma unroll
        for (int c = 0; c < N_CLASSES; c++)
            lg[c] = fmaf(pv, Wout[d * N_CLASSES + c], lg[c]);
    }
    float mx = lg[0];
    #pragma unroll
    for (int c = 1; c < N_CLASSES; c++) mx = fmaxf(mx, lg[c]);
    float sum = 0.f;
    #pragma unroll
    for (int c = 0; c < N_CLASSES; c++) sum += expf(lg[c] - mx);
    float ls = logf(sum);
    #pragma unroll
    for (int c = 0; c < N_CLASSES; c++) out[g * N_CLASSES + c] = lg[c] - mx - ls;
}

// ----------------------------- launch --------------------------------------
extern "C" void kernel_launch(void* const* d_in, const int* in_sizes, int n_in,
                              void* d_out, int out_size) {
    const float* x    = (const float*)d_in[0];
    const int*   ei   = (const int*)d_in[1];
    const int*   batch= (const int*)d_in[2];
    const float* Wl   = (const float*)d_in[3];
    const float* bl   = (const float*)d_in[4];
    const float* Wr   = (const float*)d_in[5];
    const float* brp  = (const float*)d_in[6];
    const float* att  = (const float*)d_in[7];
    const float* bias = (const float*)d_in[8];
    const float* Wout = (const float*)d_in[9];
    const float* bout = (const float*)d_in[10];
    float* out = (float*)d_out;

    cudaFuncSetAttribute(k_gemm_mma, cudaFuncAttributeMaxDynamicSharedMemorySize, GSM_TOTAL);

    k_prep<<<(N_NODES * D / 4 + 255) / 256, 256>>>(x, ei, Wl, Wr);
    k_scan<<<1, 1024>>>();
    k_fill<<<(E_TOT + 255) / 256, 256>>>(ei);

    dim3 gemm_grid((N_NODES + 127) / 128, 2);
    const int agg_blocks = (N_NODES * 32 + 255) / 256;

    for (int l = 0; l < N_LAYERS; l++) {
        k_gemm_mma<<<gemm_grid, 256, GSM_TOTAL>>>(l, bl + l * D, brp + l * D);
        k_aggregate<<<agg_blocks, 256>>>(att + l * D, bias + l * D);
    }

    k_pool<<<(N_NODES * 32 + 255) / 256, 256>>>(batch);
    k_head<<<1, 64>>>(Wout, bout, out);
}

// round 6
// speedup vs baseline: 1.3330x; 1.1566x over previous
#include <cuda_runtime.h>
#include <cuda_bf16.h>
#include <cuda_fp16.h>
#include <math.h>
#include <stdint.h>

#define N_NODES  50000
#define N_EDGES  800000
#define E_TOT    850000
#define N_GRAPHS 64
#define D        128
#define N_CLASSES 10
#define NEG_SLOPE 0.2f
#define N_LAYERS 5

// ----------------------------- scratch (device globals) --------------------
__device__ float  g_h   [N_NODES * D];
__device__ __half g_xl_h[N_NODES * D];      // fp16 xl (gather stream)
__device__ float  g_xr  [N_NODES * D];
__device__ __nv_bfloat16 g_in_hi[N_NODES * D];
__device__ __nv_bfloat16 g_in_lo[N_NODES * D];
// W fragments in per-lane mma register layout: [l2][k0][jp][lane] -> uint4
__device__ uint4 g_wfrag_hi[N_LAYERS * 2 * 8 * 8 * 32];
__device__ uint4 g_wfrag_lo[N_LAYERS * 2 * 8 * 8 * 32];
__device__ int   g_deg[N_NODES];            // zero-init at load; scan resets to 0
__device__ int   g_off[N_NODES + 1];
__device__ int   g_cur[N_NODES];
__device__ int   g_srcs[E_TOT];
__device__ float g_psum[N_GRAPHS * D];
__device__ int   g_pcnt[N_GRAPHS];

__device__ __forceinline__ float lrelu(float v) { return v > 0.f ? v : NEG_SLOPE * v; }
__device__ __forceinline__ float elu(float v)   { return v > 0.f ? v : __expf(v) - 1.f; }

__device__ __forceinline__ uint32_t smem_u32(const void* p) {
    uint32_t a;
    asm("{ .reg .u64 t; cvta.to.shared.u64 t, %1; cvt.u32.u64 %0, t; }" : "=r"(a) : "l"(p));
    return a;
}

#define LDSM_X4(R, addr) \
    asm volatile("ldmatrix.sync.aligned.m8n8.x4.shared.b16 {%0,%1,%2,%3}, [%4];" \
        : "=r"((R)[0]), "=r"((R)[1]), "=r"((R)[2]), "=r"((R)[3]) : "r"(addr))
#define MMA_BF16(C, A, B0, B1) \
    asm volatile("mma.sync.aligned.m16n8k16.row.col.f32.bf16.bf16.f32 " \
        "{%0,%1,%2,%3}, {%4,%5,%6,%7}, {%8,%9}, {%0,%1,%2,%3};" \
        : "+f"((C)[0]), "+f"((C)[1]), "+f"((C)[2]), "+f"((C)[3]) \
        : "r"((A)[0]), "r"((A)[1]), "r"((A)[2]), "r"((A)[3]), "r"(B0), "r"(B1))

// ----------------------------- fused prep -----------------------------------
__global__ void k_prep(const float* __restrict__ x, const int* __restrict__ ei,
                       const float* __restrict__ Wl, const float* __restrict__ Wr) {
    int i = blockIdx.x * blockDim.x + threadIdx.x;

    if (i < N_NODES * D / 4) {               // bf16-split of input x
        float4 v = ((const float4*)x)[i];
        __nv_bfloat16 h[4], l[4];
        float vv[4] = {v.x, v.y, v.z, v.w};
        #pragma unroll
        for (int j = 0; j < 4; j++) {
            h[j] = __float2bfloat16(vv[j]);
            l[j] = __float2bfloat16(vv[j] - __bfloat162float(h[j]));
        }
        ((uint2*)g_in_hi)[i] = *(const uint2*)h;
        ((uint2*)g_in_lo)[i] = *(const uint2*)l;
    }
    if (i < N_EDGES) atomicAdd(&g_deg[ei[N_EDGES + i]], 1);

    // W fragments: i in [0, 20480): lane|jp|k0|l2
    if (i < N_LAYERS * 2 * 8 * 8 * 32) {
        int lane = i & 31;
        int jp   = (i >> 5) & 7;
        int k0   = (i >> 8) & 7;
        int l2   = i >> 11;
        const float* W = ((l2 & 1) ? Wr : Wl) + (l2 >> 1) * D * D;
        uint32_t hi4[4], lo4[4];
        #pragma unroll
        for (int mi = 0; mi < 4; mi++) {
            int n = jp * 16 + (mi >> 1) * 8 + (lane >> 2);
            int k = k0 * 16 + (mi & 1) * 8 + 2 * (lane & 3);
            float v0 = W[k * D + n], v1 = W[(k + 1) * D + n];
            __nv_bfloat16 h0 = __float2bfloat16(v0);
            __nv_bfloat16 h1 = __float2bfloat16(v1);
            __nv_bfloat16 q0 = __float2bfloat16(v0 - __bfloat162float(h0));
            __nv_bfloat16 q1 = __float2bfloat16(v1 - __bfloat162float(h1));
            __nv_bfloat162 ph = __nv_bfloat162(h0, h1);
            __nv_bfloat162 pl = __nv_bfloat162(q0, q1);
            hi4[mi] = *(uint32_t*)&ph;
            lo4[mi] = *(uint32_t*)&pl;
        }
        g_wfrag_hi[i] = make_uint4(hi4[0], hi4[1], hi4[2], hi4[3]);
        g_wfrag_lo[i] = make_uint4(lo4[0], lo4[1], lo4[2], lo4[3]);
    }
    if (i < N_GRAPHS * D) g_psum[i] = 0.f;
    if (i < N_GRAPHS) g_pcnt[i] = 0;
}

// single-block scan; degree = g_deg + 1 (self loop); resets g_deg for next replay
__global__ void k_scan() {
    __shared__ int sh[1024];
    const int CH = (N_NODES + 1023) / 1024;
    int t = threadIdx.x;
    int beg = t * CH, end = min(beg + CH, N_NODES);
    int s = 0;
    for (int i = beg; i < end; i++) s += g_deg[i] + 1;
    sh[t] = s;
    __syncthreads();
    #pragma unroll
    for (int off = 1; off < 1024; off <<= 1) {
        int add = (t >= off) ? sh[t - off] : 0;
        __syncthreads();
        sh[t] += add;
        __syncthreads();
    }
    int run = sh[t] - s;
    for (int i = beg; i < end; i++) {
        g_off[i] = run; g_cur[i] = run;
        run += g_deg[i] + 1;
        g_deg[i] = 0;
    }
    if (t == 1023) g_off[N_NODES] = run;
}

__global__ void k_fill(const int* __restrict__ ei) {
    int e = blockIdx.x * blockDim.x + threadIdx.x;
    if (e >= E_TOT) return;
    int s, d;
    if (e < N_EDGES) { s = ei[e]; d = ei[N_EDGES + e]; }
    else             { s = d = e - N_EDGES; }
    int pos = atomicAdd(&g_cur[d], 1);
    g_srcs[pos] = s;
}

// ----------------------------- mma.sync bf16-split GEMM --------------------
// blockIdx.y: 0 -> xl (fp16 out) ; 1 -> xr (fp32 out)
// SMEM: A hi/lo tiles only (68KB) -> 2 CTAs/SM. W frags stream from gmem/L1.
#define TSTRIDE 272
#define TBYTES  (128 * TSTRIDE)
#define GSM_TOTAL (2 * TBYTES)

__global__ void __launch_bounds__(256, 2) k_gemm_mma(
    int layer, const float* __restrict__ bl, const float* __restrict__ br)
{
    extern __shared__ char smem[];
    const int tid = threadIdx.x, wid = tid >> 5, lane = tid & 31;
    const int m0 = blockIdx.x * 128;
    const int which = blockIdx.y;

    const uint4* ahi4 = (const uint4*)g_in_hi;
    const uint4* alo4 = (const uint4*)g_in_lo;
    for (int c = tid; c < 2048; c += 256) {
        int row = c >> 4, cb = c & 15;
        int gr = m0 + row;
        uint4 vh = make_uint4(0, 0, 0, 0), vl = make_uint4(0, 0, 0, 0);
        if (gr < N_NODES) { vh = ahi4[gr * 16 + cb]; vl = alo4[gr * 16 + cb]; }
        *(uint4*)(smem + row * TSTRIDE + cb * 16) = vh;
        *(uint4*)(smem + TBYTES + row * TSTRIDE + cb * 16) = vl;
    }
    __syncthreads();

    uint32_t sb = smem_u32(smem);
    uint32_t Ahi = sb, Alo = sb + TBYTES;

    float acc[16][4];
    #pragma unroll
    for (int j = 0; j < 16; j++)
        #pragma unroll
        for (int q = 0; q < 4; q++) acc[j][q] = 0.f;

    const int wrow = wid * 16;
    uint32_t a_off = (uint32_t)((wrow + (lane & 7) + ((lane >> 3) & 1) * 8) * TSTRIDE
                                + (lane >> 4) * 16);

    const uint4* whp = g_wfrag_hi + (size_t)(layer * 2 + which) * 64 * 32 + lane;
    const uint4* wlp = g_wfrag_lo + (size_t)(layer * 2 + which) * 64 * 32 + lane;

    #pragma unroll
    for (int k0 = 0; k0 < 8; k0++) {
        uint32_t ah[4], al[4];
        LDSM_X4(ah, Ahi + a_off + k0 * 32);
        LDSM_X4(al, Alo + a_off + k0 * 32);
        #pragma unroll
        for (int jp = 0; jp < 8; jp++) {
            uint4 bh = whp[(k0 * 8 + jp) * 32];
            uint4 bo = wlp[(k0 * 8 + jp) * 32];
            MMA_BF16(acc[2 * jp],     ah, bh.x, bh.y);
            MMA_BF16(acc[2 * jp + 1], ah, bh.z, bh.w);
            MMA_BF16(acc[2 * jp],     ah, bo.x, bo.y);
            MMA_BF16(acc[2 * jp + 1], ah, bo.z, bo.w);
            MMA_BF16(acc[2 * jp],     al, bh.x, bh.y);
            MMA_BF16(acc[2 * jp + 1], al, bh.z, bh.w);
        }
    }

    const float* bias = which ? br : bl;
    int r = lane >> 2, c2 = (lane & 3) * 2;
    int row0 = m0 + wrow + r, row1 = row0 + 8;
    if (which == 0) {                        // fp16 xl
        #pragma unroll
        for (int j = 0; j < 16; j++) {
            int col = j * 8 + c2;
            float b0v = bias[col], b1v = bias[col + 1];
            if (row0 < N_NODES)
                *(__half2*)(g_xl_h + (size_t)row0 * D + col) =
                    __floats2half2_rn(acc[j][0] + b0v, acc[j][1] + b1v);
            if (row1 < N_NODES)
                *(__half2*)(g_xl_h + (size_t)row1 * D + col) =
                    __floats2half2_rn(acc[j][2] + b0v, acc[j][3] + b1v);
        }
    } else {                                 // fp32 xr
        #pragma unroll
        for (int j = 0; j < 16; j++) {
            int col = j * 8 + c2;
            float b0v = bias[col], b1v = bias[col + 1];
            if (row0 < N_NODES)
                *(float2*)(g_xr + (size_t)row0 * D + col) = make_float2(acc[j][0] + b0v, acc[j][1] + b1v);
            if (row1 < N_NODES)
                *(float2*)(g_xr + (size_t)row1 * D + col) = make_float2(acc[j][2] + b0v, acc[j][3] + b1v);
        }
    }
}

// ----------------------------- fused edge phase (fp16 gather, unroll-4) -----
__device__ __forceinline__ float4 h4_to_f4(uint2 u) {
    float2 a = __half22float2(*(__half2*)&u.x);
    float2 b = __half22float2(*(__half2*)&u.y);
    return make_float4(a.x, a.y, b.x, b.y);
}

__global__ void __launch_bounds__(256) k_aggregate(
    const float* __restrict__ att, const float* __restrict__ bias)
{
    int gid  = (blockIdx.x * blockDim.x + threadIdx.x) >> 5;
    int lane = threadIdx.x & 31;
    if (gid >= N_NODES) return;

    const uint2* xl2 = (const uint2*)g_xl_h;
    float4 xr_v = ((const float4*)g_xr)[gid * 32 + lane];
    float4 a    = ((const float4*)att)[lane];

    float m = -INFINITY, s = 0.f;
    float ax = 0.f, ay = 0.f, az = 0.f, aw = 0.f;

    int e   = g_off[gid];
    int end = g_off[gid + 1];

    for (; e + 3 < end; e += 4) {
        int s0 = g_srcs[e],     s1 = g_srcs[e + 1];
        int s2 = g_srcs[e + 2], s3 = g_srcs[e + 3];
        float4 x0 = h4_to_f4(xl2[(size_t)s0 * 32 + lane]);
        float4 x1 = h4_to_f4(xl2[(size_t)s1 * 32 + lane]);
        float4 x2 = h4_to_f4(xl2[(size_t)s2 * 32 + lane]);
        float4 x3 = h4_to_f4(xl2[(size_t)s3 * 32 + lane]);
        float p0 = lrelu(x0.x + xr_v.x) * a.x + lrelu(x0.y + xr_v.y) * a.y +
                   lrelu(x0.z + xr_v.z) * a.z + lrelu(x0.w + xr_v.w) * a.w;
        float p1 = lrelu(x1.x + xr_v.x) * a.x + lrelu(x1.y + xr_v.y) * a.y +
                   lrelu(x1.z + xr_v.z) * a.z + lrelu(x1.w + xr_v.w) * a.w;
        float p2 = lrelu(x2.x + xr_v.x) * a.x + lrelu(x2.y + xr_v.y) * a.y +
                   lrelu(x2.z + xr_v.z) * a.z + lrelu(x2.w + xr_v.w) * a.w;
        float p3 = lrelu(x3.x + xr_v.x) * a.x + lrelu(x3.y + xr_v.y) * a.y +
                   lrelu(x3.z + xr_v.z) * a.z + lrelu(x3.w + xr_v.w) * a.w;
        p0 += __shfl_xor_sync(0xffffffffu, p0, 1);
        p1 += __shfl_xor_sync(0xffffffffu, p1, 1);
        p2 += __shfl_xor_sync(0xffffffffu, p2, 1);
        p3 += __shfl_xor_sync(0xffffffffu, p3, 1);
        p0 += __shfl_xor_sync(0xffffffffu, p0, 2);
        p1 += __shfl_xor_sync(0xffffffffu, p1, 2);
        p2 += __shfl_xor_sync(0xffffffffu, p2, 2);
        p3 += __shfl_xor_sync(0xffffffffu, p3, 2);
        float mn = fmaxf(fmaxf(m, fmaxf(p0, p1)), fmaxf(p2, p3));
        float sc = __expf(m - mn);
        float w0 = __expf(p0 - mn);
        float w1 = __expf(p1 - mn);
        float w2 = __expf(p2 - mn);
        float w3 = __expf(p3 - mn);
        s  = s * sc + (w0 + w1) + (w2 + w3);
        ax = ax * sc + (x0.x * w0 + x1.x * w1) + (x2.x * w2 + x3.x * w3);
        ay = ay * sc + (x0.y * w0 + x1.y * w1) + (x2.y * w2 + x3.y * w3);
        az = az * sc + (x0.z * w0 + x1.z * w1) + (x2.z * w2 + x3.z * w3);
        aw = aw * sc + (x0.w * w0 + x1.w * w1) + (x2.w * w2 + x3.w * w3);
        m = mn;
    }
    for (; e < end; e++) {
        int s0 = g_srcs[e];
        float4 x0 = h4_to_f4(xl2[(size_t)s0 * 32 + lane]);
        float p0 = lrelu(x0.x + xr_v.x) * a.x + lrelu(x0.y + xr_v.y) * a.y +
                   lrelu(x0.z + xr_v.z) * a.z + lrelu(x0.w + xr_v.w) * a.w;
        p0 += __shfl_xor_sync(0xffffffffu, p0, 1);
        p0 += __shfl_xor_sync(0xffffffffu, p0, 2);
        float mn = fmaxf(m, p0);
        float sc = __expf(m - mn);
        float w0 = __expf(p0 - mn);
        s  = s * sc + w0;
        ax = ax * sc + x0.x * w0;
        ay = ay * sc + x0.y * w0;
        az = az * sc + x0.z * w0;
        aw = aw * sc + x0.w * w0;
        m = mn;
    }

    float inv = 1.f / s;
    float4 bv = ((const float4*)bias)[lane];
    float4 o;
    o.x = elu(ax * inv + bv.x);
    o.y = elu(ay * inv + bv.y);
    o.z = elu(az * inv + bv.z);
    o.w = elu(aw * inv + bv.w);
    ((float4*)g_h)[gid * 32 + lane] = o;

    __nv_bfloat16 h[4], l[4];
    float vv[4] = {o.x, o.y, o.z, o.w};
    #pragma unroll
    for (int j = 0; j < 4; j++) {
        h[j] = __float2bfloat16(vv[j]);
        l[j] = __float2bfloat16(vv[j] - __bfloat162float(h[j]));
    }
    ((uint2*)g_in_hi)[gid * 32 + lane] = *(const uint2*)h;
    ((uint2*)g_in_lo)[gid * 32 + lane] = *(const uint2*)l;
}

// ----------------------------- pooling + classifier ------------------------
__global__ void k_pool(const int* __restrict__ batch) {
    int id = blockIdx.x * blockDim.x + threadIdx.x;
    if (id >= N_NODES * 32) return;
    int node = id >> 5, lane = id & 31;
    int g = batch[node];
    float4 v = ((const float4*)g_h)[node * 32 + lane];
    atomicAdd(&g_psum[g * D + lane * 4 + 0], v.x);
    atomicAdd(&g_psum[g * D + lane * 4 + 1], v.y);
    atomicAdd(&g_psum[g * D + lane * 4 + 2], v.z);
    atomicAdd(&g_psum[g * D + lane * 4 + 3], v.w);
    if (lane == 0) atomicAdd(&g_pcnt[g], 1);
}

__global__ void k_head(const float* __restrict__ Wout, const float* __restrict__ bout,
                       float* __restrict__ out) {
    int g = threadIdx.x;
    if (g >= N_GRAPHS) return;
    float inv = 1.f / fmaxf((float)g_pcnt[g], 1.f);
    float lg[N_CLASSES];
    #pragma unroll
    for (int c = 0; c < N_CLASSES; c++) lg[c] = bout[c];
    for (int d = 0; d < D; d++) {
        float pv = g_psum[g * D + d] * inv;
        #pragma unroll
        for (int c = 0; c < N_CLASSES; c++)
            lg[c] = fmaf(pv, Wout[d * N_CLASSES + c], lg[c]);
    }
    float mx = lg[0];
    #pragma unroll
    for (int c = 1; c < N_CLASSES; c++) mx = fmaxf(mx, lg[c]);
    float sum = 0.f;
    #pragma unroll
    for (int c = 0; c < N_CLASSES; c++) sum += expf(lg[c] - mx);
    float ls = logf(sum);
    #pragma unroll
    for (int c = 0; c < N_CLASSES; c++) out[g * N_CLASSES + c] = lg[c] - mx - ls;
}

// ----------------------------- launch --------------------------------------
extern "C" void kernel_launch(void* const* d_in, const int* in_sizes, int n_in,
                              void* d_out, int out_size) {
    const float* x    = (const float*)d_in[0];
    const int*   ei   = (const int*)d_in[1];
    const int*   batch= (const int*)d_in[2];
    const float* Wl   = (const float*)d_in[3];
    const float* bl   = (const float*)d_in[4];
    const float* Wr   = (const float*)d_in[5];
    const float* brp  = (const float*)d_in[6];
    const float* att  = (const float*)d_in[7];
    const float* bias = (const float*)d_in[8];
    const float* Wout = (const float*)d_in[9];
    const float* bout = (const float*)d_in[10];
    float* out = (float*)d_out;

    cudaFuncSetAttribute(k_gemm_mma, cudaFuncAttributeMaxDynamicSharedMemorySize, GSM_TOTAL);

    k_prep<<<(N_NODES * D / 4 + 255) / 256, 256>>>(x, ei, Wl, Wr);
    k_scan<<<1, 1024>>>();
    k_fill<<<(E_TOT + 255) / 256, 256>>>(ei);

    dim3 gemm_grid((N_NODES + 127) / 128, 2);
    const int agg_blocks = (N_NODES * 32 + 255) / 256;

    for (int l = 0; l < N_LAYERS; l++) {
        k_gemm_mma<<<gemm_grid, 256, GSM_TOTAL>>>(l, bl + l * D, brp + l * D);
        k_aggregate<<<agg_blocks, 256>>>(att + l * D, bias + l * D);
    }

    k_pool<<<(N_NODES * 32 + 255) / 256, 256>>>(batch);
    k_head<<<1, 64>>>(Wout, bout, out);
}